// round 16
// baseline (speedup 1.0000x reference)
#include <cuda_runtime.h>
#include <cuda_bf16.h>
#include <math.h>
#include <float.h>
#include <stdint.h>

#define TT   80
#define DIN  4096
#define HH   512
#define HD2  1024
#define GE   2048      /* 4*HH  */
#define VV   32000
#define KB   4
#define ML   20
#define NB   264
#define NT   256
#define NWARP (NB*8)   /* 2112 */

// ---------------- device scratch ----------------
__device__ float g_Xpre[TT*GE];
__device__ float g_Gb[GE];
__device__ float g_encH[2][HH];
__device__ float g_encC[HH];
__device__ float g_h2[2][KB*HD2];
__device__ float g_c2[2][KB*HD2];
__device__ float g_o[KB*HD2];
__device__ float g_logits[KB*VV];
__device__ int   g_tok[2][KB*(ML+1)];
__device__ float g_pmax[NB*KB];
__device__ float g_psum[NB*KB];
__device__ float g_candv[NB*KB];
__device__ int   g_candi[NB*KB];
__device__ unsigned g_Wbfu[VV*HD2/2];      // bf16-packed W_out (64 MB, L2-resident)
__device__ unsigned g_cnt = 0;
__device__ volatile unsigned g_epoch = 0;
__device__ unsigned g_cnt_e = 0;
__device__ volatile unsigned g_epoch_e = 0;

// ---------------- helpers ----------------
__device__ __forceinline__ float sigm(float x){ return 1.f/(1.f+expf(-x)); }
__device__ __forceinline__ float dot4(float4 a, float4 b){
    return a.x*b.x + a.y*b.y + a.z*b.z + a.w*b.w;
}
__device__ __forceinline__ float ftz(float x){
    return (fabsf(x) < FLT_MIN) ? 0.f : x;
}
__device__ __forceinline__ unsigned pack_bf(float lo, float hi){
    __nv_bfloat162 h = __floats2bfloat162_rn(lo, hi);
    return *(unsigned*)&h;
}

__device__ __forceinline__ bool bet(float v1,int i1,float v2,int i2){
    return (v1 > v2) || (v1 == v2 && i1 < i2);
}
__device__ __forceinline__ void ins4(float v,int i,float tv[4],int ti[4]){
    if (bet(v,i,tv[3],ti[3])){
        tv[3]=v; ti[3]=i;
        if (bet(tv[3],ti[3],tv[2],ti[2])){ float a=tv[2];int b=ti[2]; tv[2]=tv[3];ti[2]=ti[3]; tv[3]=a;ti[3]=b; }
        if (bet(tv[2],ti[2],tv[1],ti[1])){ float a=tv[1];int b=ti[1]; tv[1]=tv[2];ti[1]=ti[2]; tv[2]=a;ti[2]=b; }
        if (bet(tv[1],ti[1],tv[0],ti[0])){ float a=tv[0];int b=ti[0]; tv[0]=tv[1];ti[0]=ti[1]; tv[1]=a;ti[1]=b; }
    }
}
__device__ __forceinline__ void warp_merge4(float tv[4],int ti[4]){
    #pragma unroll
    for (int off=16; off; off>>=1){
        float ov[4]; int oi[4];
        #pragma unroll
        for (int j=0;j<4;j++){
            ov[j]=__shfl_xor_sync(0xffffffffu,tv[j],off);
            oi[j]=__shfl_xor_sync(0xffffffffu,ti[j],off);
        }
        #pragma unroll
        for (int j=0;j<4;j++) ins4(ov[j],oi[j],tv,ti);
    }
}

__device__ __forceinline__ void gbar(){
    __threadfence();
    __syncthreads();
    if (threadIdx.x == 0){
        unsigned e = g_epoch;
        if (atomicAdd(&g_cnt, 1u) == NB-1u){
            g_cnt = 0;
            __threadfence();
            g_epoch = e + 1u;
        } else {
            while (g_epoch == e) { __nanosleep(32); }
        }
    }
    __syncthreads();
    __threadfence();
}

__global__ void __launch_bounds__(NT, 2) beam_kernel(
    const float* __restrict__ video, const float* __restrict__ emb,
    const float* __restrict__ Wih_f, const float* __restrict__ Whh_f, const float* __restrict__ b_f,
    const float* __restrict__ Wih_b, const float* __restrict__ b_b,
    const float* __restrict__ dWih, const float* __restrict__ dWhh, const float* __restrict__ db,
    const float* __restrict__ Wcat, const float* __restrict__ bcat,
    const float* __restrict__ Wout, const float* __restrict__ bout,
    float* __restrict__ out, int out_size)
{
    __shared__ float4 smem4[2048];           // 32 KB staging
    float* smem = (float*)smem4;
    __shared__ float sm_m[8][KB], sm_s[8][KB];
    __shared__ float scv[8*KB];  __shared__ int sci[8*KB];
    __shared__ int   s_bi2[KB], s_tok[KB];
    __shared__ float s_bp[KB], s_gmax[KB], s_S[KB];

    const int bid = blockIdx.x, tid = threadIdx.x;
    const int wid = tid>>5, lane = tid&31;
    const int gwarp = bid*8 + wid;

    // =============== P0: init + W_out->bf16 + encoder input projections ===============
    {
        int g = bid*NT + tid;
        if (g < KB*(ML+1)) g_tok[0][g] = 1;
        if (g < HH) { g_encH[0][g] = 0.f; g_encC[g] = 0.f; }
    }
    // bf16 conversion of W_out (once); source evict-first, dest will be re-read
    {
        const int NG = VV*HD2/8;             // uint4 groups
        for (int g = bid*NT + tid; g < NG; g += NB*NT){
            const float4* src = (const float4*)Wout + 2*(size_t)g;
            float4 a = __ldcs(src), b = __ldcs(src+1);
            uint4 w;
            w.x = pack_bf(a.x, a.y);
            w.y = pack_bf(a.z, a.w);
            w.z = pack_bf(b.x, b.y);
            w.w = pack_bf(b.z, b.w);
            ((uint4*)g_Wbfu)[g] = w;
        }
    }

    for (int job = bid; job < 168; job += NB){
        if (job < 160){
            const int t0 = (job>>5)*16, j0 = (job&31)*64;
            float* Xs = smem;                // [16][65]
            float* Ws = smem + 16*65;        // [64][65]
            const int jj = tid & 63, tr = tid >> 6;
            float acc[4] = {0.f,0.f,0.f,0.f};
            for (int kc = 0; kc < DIN; kc += 64){
                __syncthreads();
                for (int i = tid; i < 16*64; i += NT){
                    int r = i>>6, kk = i&63;
                    Xs[r*65+kk] = __ldg(&video[(size_t)(t0+r)*DIN + kc+kk]);
                }
                for (int i = tid; i < 64*64; i += NT){
                    int r = i>>6, kk = i&63;
                    Ws[r*65+kk] = __ldg(&Wih_f[(size_t)(j0+r)*DIN + kc+kk]);
                }
                __syncthreads();
                #pragma unroll 8
                for (int kk = 0; kk < 64; kk++){
                    float w = Ws[jj*65+kk];
                    #pragma unroll
                    for (int u = 0; u < 4; u++)
                        acc[u] += Xs[(tr+4*u)*65+kk]*w;
                }
            }
            float bb = __ldg(&b_f[j0+jj]);
            #pragma unroll
            for (int u = 0; u < 4; u++)
                g_Xpre[(size_t)(t0+tr+4*u)*GE + j0+jj] = acc[u] + bb;
            __syncthreads();
        } else {
            const int r0 = (job-160)*256 + wid*32;
            const float4* x4 = (const float4*)(video + (size_t)(TT-1)*DIN);
            for (int rr = 0; rr < 32; rr++){
                int row = r0 + rr;
                const float4* w4 = (const float4*)(Wih_b + (size_t)row*DIN);
                float a = 0.f;
                #pragma unroll 8
                for (int q = 0; q < 32; q++)
                    a += dot4(__ldg(&w4[lane+32*q]), __ldg(&x4[lane+32*q]));
                #pragma unroll
                for (int o = 16; o; o >>= 1) a += __shfl_xor_sync(0xffffffffu,a,o);
                if (lane == 0) g_Gb[row] = a + __ldg(&b_b[row]);
            }
        }
    }
    unsigned e0 = g_epoch_e;
    gbar();

    // =============== P1: forward encoder (80 steps, blocks 0-63 only) ===============
    if (bid < 64){
        unsigned e = e0;
        for (int t = 0; t < TT; t++){
            const float* hin = g_encH[t&1];
            for (int i = tid; i < HH; i += NT) smem[i] = __ldcg(&hin[i]);
            __syncthreads();
            const int j = bid*8 + wid;
            const float4* h4 = (const float4*)smem;
            float acc[4];
            #pragma unroll
            for (int g = 0; g < 4; g++){
                const float4* w4 = (const float4*)(Whh_f + (size_t)(g*HH + j)*HH);
                float a = 0.f;
                #pragma unroll
                for (int q = 0; q < 4; q++)
                    a += dot4(__ldg(&w4[lane+32*q]), h4[lane+32*q]);
                acc[g] = a;
            }
            #pragma unroll
            for (int o = 16; o; o >>= 1)
                #pragma unroll
                for (int g = 0; g < 4; g++)
                    acc[g] += __shfl_xor_sync(0xffffffffu, acc[g], o);
            if (lane == 0){
                float gi = acc[0] + __ldcg(&g_Xpre[(size_t)t*GE + j]);
                float gf = acc[1] + __ldcg(&g_Xpre[(size_t)t*GE + HH + j]);
                float gg = acc[2] + __ldcg(&g_Xpre[(size_t)t*GE + 2*HH + j]);
                float go = acc[3] + __ldcg(&g_Xpre[(size_t)t*GE + 3*HH + j]);
                float c2 = sigm(gf)*__ldcg(&g_encC[j]) + sigm(gi)*tanhf(gg);
                float h2 = sigm(go)*tanhf(c2);
                g_encC[j] = c2;
                g_encH[(t+1)&1][j] = h2;
            }
            __threadfence();
            __syncthreads();
            if (tid == 0){
                if (atomicAdd(&g_cnt_e, 1u) == 63u){
                    g_cnt_e = 0;
                    __threadfence();
                    g_epoch_e = e + 1u;
                } else {
                    while (g_epoch_e == e) { __nanosleep(32); }
                }
            }
            __syncthreads();
            __threadfence();
            e = e + 1u;
        }
    } else {
        if (tid == 0){
            while ((unsigned)(g_epoch_e - e0) < (unsigned)TT) { __nanosleep(256); }
        }
        __syncthreads();
        __threadfence();
    }
    gbar();

    // =============== P2: decoder init ===============
    {
        int g = bid*NT + tid;
        if (g < HH){
            float hf = __ldcg(&g_encH[0][g]);
            float gi = __ldcg(&g_Gb[g]);
            float gg = __ldcg(&g_Gb[2*HH+g]);
            float go = __ldcg(&g_Gb[3*HH+g]);
            float cb = sigm(gi)*tanhf(gg);
            float hb = sigm(go)*tanhf(cb);
            #pragma unroll
            for (int k = 0; k < KB; k++){
                g_h2[0][k*HD2 + g]      = hf;
                g_h2[0][k*HD2 + HH + g] = hb;
            }
        }
        for (int i = g; i < KB*HD2; i += NB*NT) g_c2[0][i] = 0.f;
    }
    gbar();

    // =============== P3: decoder beam search (20 steps) ===============
    float4* xs = smem4;            // [4][256] f4
    float4* hs = smem4 + 4*256;    // [4][256] f4

    for (int t = 0; t < ML; t++){
        const int cur = t & 1, nxt = (t+1) & 1;

        // -------- SEL --------
        if (t == 0){
            if (tid < KB){ s_bi2[tid]=tid; s_tok[tid]=1; s_bp[tid]=(tid==0)?1.f:0.f; }
            __syncthreads();
        } else {
            if (wid == 0){
                float tv[4] = {-FLT_MAX,-FLT_MAX,-FLT_MAX,-FLT_MAX};
                int   ti[4] = {0x7fffffff,0x7fffffff,0x7fffffff,0x7fffffff};
                for (int i = lane; i < NB*KB; i += 32)
                    ins4(__ldcg(&g_candv[i]), __ldcg(&g_candi[i]), tv, ti);
                warp_merge4(tv, ti);
                if (lane == 0)
                    #pragma unroll
                    for (int j = 0; j < 4; j++){
                        int idx = ti[j];
                        s_bi2[j] = idx / VV;
                        s_tok[j] = idx - (idx/VV)*VV;
                        s_bp[j]  = tv[j];
                    }
            }
            __syncthreads();
            if (bid == 0 && tid < KB*(ML+1)){
                int kk = tid/(ML+1), col = tid%(ML+1);
                int val = (col == t) ? s_tok[kk]
                                     : g_tok[(t-1)&1][s_bi2[kk]*(ML+1)+col];
                g_tok[t&1][tid] = val;
            }
        }

        // -------- A: decoder LSTM cell --------
        for (int i = tid; i < KB*HD2; i += NT){
            int k = i>>10, j = i&1023;
            ((float*)xs)[i] = __ldg(&emb[(size_t)s_tok[k]*HD2 + j]);
            ((float*)hs)[i] = __ldcg(&g_h2[cur][s_bi2[k]*HD2 + j]);
        }
        __syncthreads();
        for (int j = gwarp; j < HD2; j += NWARP){
            float acc[4][KB];
            #pragma unroll
            for (int g = 0; g < 4; g++)
                #pragma unroll
                for (int k = 0; k < KB; k++) acc[g][k] = 0.f;
            #pragma unroll 2
            for (int q = 0; q < 8; q++){
                int m = lane + 32*q;
                #pragma unroll
                for (int g = 0; g < 4; g++){
                    float4 wi = __ldg((const float4*)(dWih + (size_t)(g*HD2+j)*HD2) + m);
                    float4 wh = __ldg((const float4*)(dWhh + (size_t)(g*HD2+j)*HD2) + m);
                    #pragma unroll
                    for (int k = 0; k < KB; k++)
                        acc[g][k] += dot4(wi, xs[k*256+m]) + dot4(wh, hs[k*256+m]);
                }
            }
            #pragma unroll
            for (int o = 16; o; o >>= 1)
                #pragma unroll
                for (int g = 0; g < 4; g++)
                    #pragma unroll
                    for (int k = 0; k < KB; k++)
                        acc[g][k] += __shfl_xor_sync(0xffffffffu, acc[g][k], o);
            if (lane == 0){
                float bi_ = __ldg(&db[j]),       bf_ = __ldg(&db[HD2+j]);
                float bg_ = __ldg(&db[2*HD2+j]), bo_ = __ldg(&db[3*HD2+j]);
                #pragma unroll
                for (int k = 0; k < KB; k++){
                    float gi = acc[0][k]+bi_, gf = acc[1][k]+bf_;
                    float gg = acc[2][k]+bg_, go = acc[3][k]+bo_;
                    float cp = __ldcg(&g_c2[cur][s_bi2[k]*HD2 + j]);
                    float c2 = sigm(gf)*cp + sigm(gi)*tanhf(gg);
                    float h2 = sigm(go)*tanhf(c2);
                    g_c2[nxt][k*HD2+j] = c2;
                    g_h2[nxt][k*HD2+j] = h2;
                }
            }
        }
        gbar();

        // -------- B: o = tanh(W_cat @ [h2, x] + b_cat) --------
        for (int i = tid; i < KB*HD2; i += NT) ((float*)hs)[i] = __ldcg(&g_h2[nxt][i]);
        __syncthreads();
        for (int j = gwarp; j < HD2; j += NWARP){
            float acc[KB] = {0.f,0.f,0.f,0.f};
            const float4* wr = (const float4*)(Wcat + (size_t)j*(2*HD2));
            #pragma unroll 2
            for (int q = 0; q < 8; q++){
                int m = lane + 32*q;
                float4 w1 = __ldg(&wr[m]);
                float4 w2 = __ldg(&wr[256+m]);
                #pragma unroll
                for (int k = 0; k < KB; k++)
                    acc[k] += dot4(w1, hs[k*256+m]) + dot4(w2, xs[k*256+m]);
            }
            #pragma unroll
            for (int o = 16; o; o >>= 1)
                #pragma unroll
                for (int k = 0; k < KB; k++)
                    acc[k] += __shfl_xor_sync(0xffffffffu, acc[k], o);
            if (lane == 0){
                float bb = __ldg(&bcat[j]);
                #pragma unroll
                for (int k = 0; k < KB; k++)
                    g_o[k*HD2+j] = tanhf(acc[k] + bb);
            }
        }
        gbar();

        // -------- C: logits from L2-resident bf16 W_out (4 rows/warp) --------
        float4* os = smem4;   // [4][256]
        for (int i = tid; i < KB*HD2; i += NT) ((float*)os)[i] = __ldcg(&g_o[i]);
        __syncthreads();
        {
            float mw[KB] = {-FLT_MAX,-FLT_MAX,-FLT_MAX,-FLT_MAX};
            float sw[KB] = {0.f,0.f,0.f,0.f};
            for (int v0 = gwarp*4; v0 < VV; v0 += NWARP*4){
                float acc[4][KB];
                #pragma unroll
                for (int r = 0; r < 4; r++)
                    #pragma unroll
                    for (int k = 0; k < KB; k++) acc[r][k] = 0.f;
                #pragma unroll
                for (int q = 0; q < 4; q++){
                    int m = lane + 32*q;             // uint4 index (8 elems each)
                    float4 oa[KB], ob[KB];
                    #pragma unroll
                    for (int k = 0; k < KB; k++){
                        oa[k] = os[k*256 + 2*m];
                        ob[k] = os[k*256 + 2*m + 1];
                    }
                    #pragma unroll
                    for (int r = 0; r < 4; r++){
                        uint4 w = __ldg((const uint4*)g_Wbfu + (size_t)(v0+r)*128 + m);
                        float c0 = __uint_as_float(w.x << 16);
                        float c1 = __uint_as_float(w.x & 0xffff0000u);
                        float c2 = __uint_as_float(w.y << 16);
                        float c3 = __uint_as_float(w.y & 0xffff0000u);
                        float c4 = __uint_as_float(w.z << 16);
                        float c5 = __uint_as_float(w.z & 0xffff0000u);
                        float c6 = __uint_as_float(w.w << 16);
                        float c7 = __uint_as_float(w.w & 0xffff0000u);
                        #pragma unroll
                        for (int k = 0; k < KB; k++){
                            acc[r][k] += c0*oa[k].x + c1*oa[k].y + c2*oa[k].z + c3*oa[k].w
                                       + c4*ob[k].x + c5*ob[k].y + c6*ob[k].z + c7*ob[k].w;
                        }
                    }
                }
                #pragma unroll
                for (int o = 16; o; o >>= 1)
                    #pragma unroll
                    for (int r = 0; r < 4; r++)
                        #pragma unroll
                        for (int k = 0; k < KB; k++)
                            acc[r][k] += __shfl_xor_sync(0xffffffffu, acc[r][k], o);
                if (lane == 0){
                    #pragma unroll
                    for (int r = 0; r < 4; r++){
                        float bo = __ldg(&bout[v0+r]);
                        #pragma unroll
                        for (int k = 0; k < KB; k++){
                            float l = acc[r][k] + bo;
                            g_logits[(size_t)k*VV + v0 + r] = l;
                            if (l > mw[k]){ sw[k] = sw[k]*expf(mw[k]-l) + 1.f; mw[k] = l; }
                            else          { sw[k] += expf(l - mw[k]); }
                        }
                    }
                }
            }
            if (lane == 0)
                #pragma unroll
                for (int k = 0; k < KB; k++){ sm_m[wid][k] = mw[k]; sm_s[wid][k] = sw[k]; }
            __syncthreads();
            if (tid < KB){
                const int k = tid;
                float m = -FLT_MAX, s = 0.f;
                #pragma unroll
                for (int w = 0; w < 8; w++){
                    float mwv = sm_m[w][k], swv = sm_s[w][k];
                    if (mwv > m){ s = s*expf(m-mwv) + swv; m = mwv; }
                    else        { s += swv*expf(mwv-m); }
                }
                g_pmax[bid*KB+k] = m;
                g_psum[bid*KB+k] = s;
            }
        }
        gbar();

        // -------- E: global (m,S); sc=ftz chain; per-block top-4 --------
        if (wid < KB){
            const int k = wid;
            float mloc = -FLT_MAX;
            for (int i = lane; i < NB; i += 32)
                mloc = fmaxf(mloc, __ldcg(&g_pmax[i*KB+k]));
            #pragma unroll
            for (int o = 16; o; o >>= 1) mloc = fmaxf(mloc, __shfl_xor_sync(0xffffffffu, mloc, o));
            float sloc = 0.f;
            for (int i = lane; i < NB; i += 32){
                float mb = __ldcg(&g_pmax[i*KB+k]);
                float sb = __ldcg(&g_psum[i*KB+k]);
                sloc += sb*expf(mb - mloc);
            }
            #pragma unroll
            for (int o = 16; o; o >>= 1) sloc += __shfl_xor_sync(0xffffffffu, sloc, o);
            if (lane == 0){ s_gmax[k] = mloc; s_S[k] = sloc; }
        }
        __syncthreads();
        {
            float tv[4] = {-FLT_MAX,-FLT_MAX,-FLT_MAX,-FLT_MAX};
            int   ti[4] = {0x7fffffff,0x7fffffff,0x7fffffff,0x7fffffff};
            for (int v = bid*NT + tid; v < VV; v += NB*NT){
                #pragma unroll
                for (int k = 0; k < KB; k++){
                    float l  = __ldcg(&g_logits[(size_t)k*VV+v]);
                    float e  = ftz(expf(l - s_gmax[k]));
                    float pf = ftz(__fdiv_rn(e, s_S[k]));
                    float sc = ftz(__fmul_rn(s_bp[k], pf));
                    ins4(sc, k*VV+v, tv, ti);
                }
            }
            warp_merge4(tv, ti);
            if (lane == 0)
                #pragma unroll
                for (int j = 0; j < 4; j++){ scv[wid*4+j]=tv[j]; sci[wid*4+j]=ti[j]; }
            __syncthreads();
            if (tid == 0){
                float bv[4] = {-FLT_MAX,-FLT_MAX,-FLT_MAX,-FLT_MAX};
                int   bix[4] = {0x7fffffff,0x7fffffff,0x7fffffff,0x7fffffff};
                for (int i = 0; i < 32; i++) ins4(scv[i], sci[i], bv, bix);
                #pragma unroll
                for (int j = 0; j < 4; j++){ g_candv[bid*4+j]=bv[j]; g_candi[bid*4+j]=bix[j]; }
            }
        }
        gbar();
    }

    // =============== final selection + output ===============
    if (wid == 0){
        float tv[4] = {-FLT_MAX,-FLT_MAX,-FLT_MAX,-FLT_MAX};
        int   ti[4] = {0x7fffffff,0x7fffffff,0x7fffffff,0x7fffffff};
        for (int i = lane; i < NB*KB; i += 32)
            ins4(__ldcg(&g_candv[i]), __ldcg(&g_candi[i]), tv, ti);
        warp_merge4(tv, ti);
        if (lane == 0)
            #pragma unroll
            for (int j = 0; j < 4; j++){
                int idx = ti[j];
                s_bi2[j] = idx / VV;
                s_tok[j] = idx - (idx/VV)*VV;
                s_bp[j]  = tv[j];
            }
    }
    __syncthreads();
    if (bid == 0){
        if (tid < KB*(ML+1)){
            int kk = tid/(ML+1), col = tid%(ML+1);
            int val = (col == ML) ? s_tok[kk]
                                  : g_tok[(ML-1)&1][s_bi2[kk]*(ML+1)+col];
            out[tid] = (float)val;
        }
        if (out_size >= KB*(ML+1)+KB && tid < KB)
            out[KB*(ML+1)+tid] = s_bp[tid];
    }
}

// ---------------- host ----------------
static int pick_idx(const int* sz, int n, int want, int occ){
    int c = 0;
    for (int i = 0; i < n; i++)
        if (sz[i] == want){ if (c == occ) return i; c++; }
    return -1;
}

extern "C" void kernel_launch(void* const* d_in, const int* in_sizes, int n_in,
                              void* d_out, int out_size)
{
    int iv   = pick_idx(in_sizes, n_in, TT*DIN, 0);
    int ie   = pick_idx(in_sizes, n_in, VV*HD2, 0);
    int iWf  = pick_idx(in_sizes, n_in, GE*DIN, 0);
    int iHf  = pick_idx(in_sizes, n_in, GE*HH, 0);
    int ibf  = pick_idx(in_sizes, n_in, GE, 0);
    int iWb  = pick_idx(in_sizes, n_in, GE*DIN, 1);
    int ibb  = pick_idx(in_sizes, n_in, GE, 1);
    int idW  = pick_idx(in_sizes, n_in, 4*HD2*HD2, 0);
    int idH  = pick_idx(in_sizes, n_in, 4*HD2*HD2, 1);
    int idb  = pick_idx(in_sizes, n_in, 4*HD2, 0);
    int iWc  = pick_idx(in_sizes, n_in, HD2*2*HD2, 0);
    int ibc  = pick_idx(in_sizes, n_in, HD2, 0);
    int iWo  = pick_idx(in_sizes, n_in, VV*HD2, 1);
    int ibo  = pick_idx(in_sizes, n_in, VV, 0);
    if (iv<0||ie<0||iWf<0||iHf<0||ibf<0||iWb<0||ibb<0||idW<0||idH<0||idb<0||iWc<0||ibc<0||iWo<0||ibo<0){
        iv=0; ie=1; iWf=2; iHf=3; ibf=4; iWb=5; ibb=7; idW=8; idH=9; idb=10; iWc=11; ibc=12; iWo=13; ibo=14;
    }
    beam_kernel<<<NB, NT>>>(
        (const float*)d_in[iv],  (const float*)d_in[ie],
        (const float*)d_in[iWf], (const float*)d_in[iHf], (const float*)d_in[ibf],
        (const float*)d_in[iWb], (const float*)d_in[ibb],
        (const float*)d_in[idW], (const float*)d_in[idH], (const float*)d_in[idb],
        (const float*)d_in[iWc], (const float*)d_in[ibc],
        (const float*)d_in[iWo], (const float*)d_in[ibo],
        (float*)d_out, out_size);
}

// round 17
// speedup vs baseline: 1.0822x; 1.0822x over previous
#include <cuda_runtime.h>
#include <cuda_bf16.h>
#include <math.h>
#include <float.h>
#include <stdint.h>

#define TT   80
#define DIN  4096
#define HH   512
#define HD2  1024
#define GE   2048      /* 4*HH  */
#define VV   32000
#define KB   4
#define ML   20
#define NB   264
#define NT   256
#define NWARP (NB*8)   /* 2112 */

// ---------------- device scratch ----------------
__device__ float g_Xpre[TT*GE];
__device__ float g_Gb[GE];
__device__ float g_encH[2][HH];
__device__ float g_encC[HH];
__device__ float g_h2[2][KB*HD2];
__device__ float g_c2[2][KB*HD2];
__device__ float g_o[KB*HD2];
__device__ float g_logits[KB*VV];
__device__ int   g_tok[2][KB*(ML+1)];
__device__ float g_pmax[NB*KB];
__device__ float g_psum[NB*KB];
__device__ float g_candv[NB*KB];
__device__ int   g_candi[NB*KB];
__device__ unsigned g_Wbfu[VV*HD2/2];        // bf16 W_out   (64 MB)
__device__ unsigned g_dWihbf[4*HD2*HD2/2];   // bf16 dec_Wih (8 MB)
__device__ unsigned g_dWhhbf[4*HD2*HD2/2];   // bf16 dec_Whh (8 MB)
__device__ unsigned g_Wcatbf[HD2*2*HD2/2];   // bf16 W_cat   (4 MB)
__device__ unsigned g_cnt = 0;
__device__ volatile unsigned g_epoch = 0;
__device__ unsigned g_cnt_e = 0;
__device__ volatile unsigned g_epoch_e = 0;

// ---------------- helpers ----------------
__device__ __forceinline__ float sigm(float x){ return 1.f/(1.f+expf(-x)); }
__device__ __forceinline__ float dot4(float4 a, float4 b){
    return a.x*b.x + a.y*b.y + a.z*b.z + a.w*b.w;
}
__device__ __forceinline__ float ftz(float x){
    return (fabsf(x) < FLT_MIN) ? 0.f : x;
}
__device__ __forceinline__ unsigned pack_bf(float lo, float hi){
    __nv_bfloat162 h = __floats2bfloat162_rn(lo, hi);
    return *(unsigned*)&h;
}
// unpack uint4 (8 bf16) into 8 floats; c[0] is lowest-address element
__device__ __forceinline__ void unpk8(uint4 w, float* c){
    c[0]=__uint_as_float(w.x<<16); c[1]=__uint_as_float(w.x&0xffff0000u);
    c[2]=__uint_as_float(w.y<<16); c[3]=__uint_as_float(w.y&0xffff0000u);
    c[4]=__uint_as_float(w.z<<16); c[5]=__uint_as_float(w.z&0xffff0000u);
    c[6]=__uint_as_float(w.w<<16); c[7]=__uint_as_float(w.w&0xffff0000u);
}
__device__ __forceinline__ void conv_bf(const float* src, unsigned* dst,
                                        int ngroups, int g0, int gs){
    for (int g = g0; g < ngroups; g += gs){
        const float4* s = (const float4*)src + 2*(size_t)g;
        float4 a = __ldcs(s), b = __ldcs(s+1);
        uint4 w;
        w.x = pack_bf(a.x, a.y);
        w.y = pack_bf(a.z, a.w);
        w.z = pack_bf(b.x, b.y);
        w.w = pack_bf(b.z, b.w);
        ((uint4*)dst)[g] = w;
    }
}

__device__ __forceinline__ bool bet(float v1,int i1,float v2,int i2){
    return (v1 > v2) || (v1 == v2 && i1 < i2);
}
__device__ __forceinline__ void ins4(float v,int i,float tv[4],int ti[4]){
    if (bet(v,i,tv[3],ti[3])){
        tv[3]=v; ti[3]=i;
        if (bet(tv[3],ti[3],tv[2],ti[2])){ float a=tv[2];int b=ti[2]; tv[2]=tv[3];ti[2]=ti[3]; tv[3]=a;ti[3]=b; }
        if (bet(tv[2],ti[2],tv[1],ti[1])){ float a=tv[1];int b=ti[1]; tv[1]=tv[2];ti[1]=ti[2]; tv[2]=a;ti[2]=b; }
        if (bet(tv[1],ti[1],tv[0],ti[0])){ float a=tv[0];int b=ti[0]; tv[0]=tv[1];ti[0]=ti[1]; tv[1]=a;ti[1]=b; }
    }
}
__device__ __forceinline__ void warp_merge4(float tv[4],int ti[4]){
    #pragma unroll
    for (int off=16; off; off>>=1){
        float ov[4]; int oi[4];
        #pragma unroll
        for (int j=0;j<4;j++){
            ov[j]=__shfl_xor_sync(0xffffffffu,tv[j],off);
            oi[j]=__shfl_xor_sync(0xffffffffu,ti[j],off);
        }
        #pragma unroll
        for (int j=0;j<4;j++) ins4(ov[j],oi[j],tv,ti);
    }
}

__device__ __forceinline__ void gbar(){
    __threadfence();
    __syncthreads();
    if (threadIdx.x == 0){
        unsigned e = g_epoch;
        if (atomicAdd(&g_cnt, 1u) == NB-1u){
            g_cnt = 0;
            __threadfence();
            g_epoch = e + 1u;
        } else {
            while (g_epoch == e) { __nanosleep(32); }
        }
    }
    __syncthreads();
    __threadfence();
}

__global__ void __launch_bounds__(NT, 2) beam_kernel(
    const float* __restrict__ video, const float* __restrict__ emb,
    const float* __restrict__ Wih_f, const float* __restrict__ Whh_f, const float* __restrict__ b_f,
    const float* __restrict__ Wih_b, const float* __restrict__ b_b,
    const float* __restrict__ dWih, const float* __restrict__ dWhh, const float* __restrict__ db,
    const float* __restrict__ Wcat, const float* __restrict__ bcat,
    const float* __restrict__ Wout, const float* __restrict__ bout,
    float* __restrict__ out, int out_size)
{
    __shared__ float4 smem4[2048];           // 32 KB staging
    float* smem = (float*)smem4;
    __shared__ float sm_m[8][KB], sm_s[8][KB];
    __shared__ float scv[8*KB];  __shared__ int sci[8*KB];
    __shared__ int   s_bi2[KB], s_tok[KB];
    __shared__ float s_bp[KB], s_gmax[KB], s_S[KB];

    const int bid = blockIdx.x, tid = threadIdx.x;
    const int wid = tid>>5, lane = tid&31;
    const int gwarp = bid*8 + wid;

    // =============== P0: init + bf16 conversions + encoder input projections ===============
    {
        int g = bid*NT + tid;
        if (g < KB*(ML+1)) g_tok[0][g] = 1;
        if (g < HH) { g_encH[0][g] = 0.f; g_encC[g] = 0.f; }
    }
    {
        const int gg = bid*NT + tid, gs = NB*NT;
        conv_bf(Wout, g_Wbfu,   VV*HD2/8,     gg, gs);
        conv_bf(dWih, g_dWihbf, 4*HD2*HD2/8,  gg, gs);
        conv_bf(dWhh, g_dWhhbf, 4*HD2*HD2/8,  gg, gs);
        conv_bf(Wcat, g_Wcatbf, HD2*2*HD2/8,  gg, gs);
    }

    for (int job = bid; job < 168; job += NB){
        if (job < 160){
            const int t0 = (job>>5)*16, j0 = (job&31)*64;
            float* Xs = smem;                // [16][65]
            float* Ws = smem + 16*65;        // [64][65]
            const int jj = tid & 63, tr = tid >> 6;
            float acc[4] = {0.f,0.f,0.f,0.f};
            for (int kc = 0; kc < DIN; kc += 64){
                __syncthreads();
                for (int i = tid; i < 16*64; i += NT){
                    int r = i>>6, kk = i&63;
                    Xs[r*65+kk] = __ldg(&video[(size_t)(t0+r)*DIN + kc+kk]);
                }
                for (int i = tid; i < 64*64; i += NT){
                    int r = i>>6, kk = i&63;
                    Ws[r*65+kk] = __ldg(&Wih_f[(size_t)(j0+r)*DIN + kc+kk]);
                }
                __syncthreads();
                #pragma unroll 8
                for (int kk = 0; kk < 64; kk++){
                    float w = Ws[jj*65+kk];
                    #pragma unroll
                    for (int u = 0; u < 4; u++)
                        acc[u] += Xs[(tr+4*u)*65+kk]*w;
                }
            }
            float bb = __ldg(&b_f[j0+jj]);
            #pragma unroll
            for (int u = 0; u < 4; u++)
                g_Xpre[(size_t)(t0+tr+4*u)*GE + j0+jj] = acc[u] + bb;
            __syncthreads();
        } else {
            const int r0 = (job-160)*256 + wid*32;
            const float4* x4 = (const float4*)(video + (size_t)(TT-1)*DIN);
            for (int rr = 0; rr < 32; rr++){
                int row = r0 + rr;
                const float4* w4 = (const float4*)(Wih_b + (size_t)row*DIN);
                float a = 0.f;
                #pragma unroll 8
                for (int q = 0; q < 32; q++)
                    a += dot4(__ldg(&w4[lane+32*q]), __ldg(&x4[lane+32*q]));
                #pragma unroll
                for (int o = 16; o; o >>= 1) a += __shfl_xor_sync(0xffffffffu,a,o);
                if (lane == 0) g_Gb[row] = a + __ldg(&b_b[row]);
            }
        }
    }
    unsigned e0 = g_epoch_e;
    gbar();

    // =============== P1: forward encoder (80 steps, blocks 0-63 only) ===============
    if (bid < 64){
        unsigned e = e0;
        for (int t = 0; t < TT; t++){
            const float* hin = g_encH[t&1];
            for (int i = tid; i < HH; i += NT) smem[i] = __ldcg(&hin[i]);
            __syncthreads();
            const int j = bid*8 + wid;
            const float4* h4 = (const float4*)smem;
            float acc[4];
            #pragma unroll
            for (int g = 0; g < 4; g++){
                const float4* w4 = (const float4*)(Whh_f + (size_t)(g*HH + j)*HH);
                float a = 0.f;
                #pragma unroll
                for (int q = 0; q < 4; q++)
                    a += dot4(__ldg(&w4[lane+32*q]), h4[lane+32*q]);
                acc[g] = a;
            }
            #pragma unroll
            for (int o = 16; o; o >>= 1)
                #pragma unroll
                for (int g = 0; g < 4; g++)
                    acc[g] += __shfl_xor_sync(0xffffffffu, acc[g], o);
            if (lane == 0){
                float gi = acc[0] + __ldcg(&g_Xpre[(size_t)t*GE + j]);
                float gf = acc[1] + __ldcg(&g_Xpre[(size_t)t*GE + HH + j]);
                float gg = acc[2] + __ldcg(&g_Xpre[(size_t)t*GE + 2*HH + j]);
                float go = acc[3] + __ldcg(&g_Xpre[(size_t)t*GE + 3*HH + j]);
                float c2 = sigm(gf)*__ldcg(&g_encC[j]) + sigm(gi)*tanhf(gg);
                float h2 = sigm(go)*tanhf(c2);
                g_encC[j] = c2;
                g_encH[(t+1)&1][j] = h2;
            }
            __threadfence();
            __syncthreads();
            if (tid == 0){
                if (atomicAdd(&g_cnt_e, 1u) == 63u){
                    g_cnt_e = 0;
                    __threadfence();
                    g_epoch_e = e + 1u;
                } else {
                    while (g_epoch_e == e) { __nanosleep(32); }
                }
            }
            __syncthreads();
            __threadfence();
            e = e + 1u;
        }
    } else {
        if (tid == 0){
            while ((unsigned)(g_epoch_e - e0) < (unsigned)TT) { __nanosleep(256); }
        }
        __syncthreads();
        __threadfence();
    }
    gbar();

    // =============== P2: decoder init ===============
    {
        int g = bid*NT + tid;
        if (g < HH){
            float hf = __ldcg(&g_encH[0][g]);
            float gi = __ldcg(&g_Gb[g]);
            float gg = __ldcg(&g_Gb[2*HH+g]);
            float go = __ldcg(&g_Gb[3*HH+g]);
            float cb = sigm(gi)*tanhf(gg);
            float hb = sigm(go)*tanhf(cb);
            #pragma unroll
            for (int k = 0; k < KB; k++){
                g_h2[0][k*HD2 + g]      = hf;
                g_h2[0][k*HD2 + HH + g] = hb;
            }
        }
        for (int i = g; i < KB*HD2; i += NB*NT) g_c2[0][i] = 0.f;
    }
    gbar();

    // =============== P3: decoder beam search (20 steps) ===============
    float4* xs = smem4;            // [4][256] f4
    float4* hs = smem4 + 4*256;    // [4][256] f4

    for (int t = 0; t < ML; t++){
        const int cur = t & 1, nxt = (t+1) & 1;

        // -------- SEL --------
        if (t == 0){
            if (tid < KB){ s_bi2[tid]=tid; s_tok[tid]=1; s_bp[tid]=(tid==0)?1.f:0.f; }
            __syncthreads();
        } else {
            if (wid == 0){
                float tv[4] = {-FLT_MAX,-FLT_MAX,-FLT_MAX,-FLT_MAX};
                int   ti[4] = {0x7fffffff,0x7fffffff,0x7fffffff,0x7fffffff};
                for (int i = lane; i < NB*KB; i += 32)
                    ins4(__ldcg(&g_candv[i]), __ldcg(&g_candi[i]), tv, ti);
                warp_merge4(tv, ti);
                if (lane == 0)
                    #pragma unroll
                    for (int j = 0; j < 4; j++){
                        int idx = ti[j];
                        s_bi2[j] = idx / VV;
                        s_tok[j] = idx - (idx/VV)*VV;
                        s_bp[j]  = tv[j];
                    }
            }
            __syncthreads();
            if (bid == 0 && tid < KB*(ML+1)){
                int kk = tid/(ML+1), col = tid%(ML+1);
                int val = (col == t) ? s_tok[kk]
                                     : g_tok[(t-1)&1][s_bi2[kk]*(ML+1)+col];
                g_tok[t&1][tid] = val;
            }
        }

        // -------- A: decoder LSTM cell (bf16 weights) --------
        for (int i = tid; i < KB*HD2; i += NT){
            int k = i>>10, j = i&1023;
            ((float*)xs)[i] = __ldg(&emb[(size_t)s_tok[k]*HD2 + j]);
            ((float*)hs)[i] = __ldcg(&g_h2[cur][s_bi2[k]*HD2 + j]);
        }
        __syncthreads();
        for (int j = gwarp; j < HD2; j += NWARP){
            float acc[4][KB];
            #pragma unroll
            for (int g = 0; g < 4; g++)
                #pragma unroll
                for (int k = 0; k < KB; k++) acc[g][k] = 0.f;
            #pragma unroll
            for (int q = 0; q < 4; q++){
                int m = lane + 32*q;                 // uint4 index, 8 elems each
                #pragma unroll
                for (int g = 0; g < 4; g++){
                    uint4 wiu = __ldg((const uint4*)g_dWihbf + (size_t)(g*HD2+j)*128 + m);
                    uint4 whu = __ldg((const uint4*)g_dWhhbf + (size_t)(g*HD2+j)*128 + m);
                    float ci[8], ch[8];
                    unpk8(wiu, ci); unpk8(whu, ch);
                    #pragma unroll
                    for (int k = 0; k < KB; k++){
                        float4 xa = xs[k*256+2*m], xb = xs[k*256+2*m+1];
                        float4 ha = hs[k*256+2*m], hb = hs[k*256+2*m+1];
                        acc[g][k] += ci[0]*xa.x + ci[1]*xa.y + ci[2]*xa.z + ci[3]*xa.w
                                   + ci[4]*xb.x + ci[5]*xb.y + ci[6]*xb.z + ci[7]*xb.w
                                   + ch[0]*ha.x + ch[1]*ha.y + ch[2]*ha.z + ch[3]*ha.w
                                   + ch[4]*hb.x + ch[5]*hb.y + ch[6]*hb.z + ch[7]*hb.w;
                    }
                }
            }
            #pragma unroll
            for (int o = 16; o; o >>= 1)
                #pragma unroll
                for (int g = 0; g < 4; g++)
                    #pragma unroll
                    for (int k = 0; k < KB; k++)
                        acc[g][k] += __shfl_xor_sync(0xffffffffu, acc[g][k], o);
            if (lane == 0){
                float bi_ = __ldg(&db[j]),       bf_ = __ldg(&db[HD2+j]);
                float bg_ = __ldg(&db[2*HD2+j]), bo_ = __ldg(&db[3*HD2+j]);
                #pragma unroll
                for (int k = 0; k < KB; k++){
                    float gi = acc[0][k]+bi_, gf = acc[1][k]+bf_;
                    float gg = acc[2][k]+bg_, go = acc[3][k]+bo_;
                    float cp = __ldcg(&g_c2[cur][s_bi2[k]*HD2 + j]);
                    float c2 = sigm(gf)*cp + sigm(gi)*tanhf(gg);
                    float h2 = sigm(go)*tanhf(c2);
                    g_c2[nxt][k*HD2+j] = c2;
                    g_h2[nxt][k*HD2+j] = h2;
                }
            }
        }
        gbar();

        // -------- B: o = tanh(W_cat @ [h2, x] + b_cat)  (bf16 W_cat) --------
        for (int i = tid; i < KB*HD2; i += NT) ((float*)hs)[i] = __ldcg(&g_h2[nxt][i]);
        __syncthreads();
        for (int j = gwarp; j < HD2; j += NWARP){
            float acc[KB] = {0.f,0.f,0.f,0.f};
            const uint4* wr = (const uint4*)g_Wcatbf + (size_t)j*256;
            #pragma unroll
            for (int q = 0; q < 4; q++){
                int m = lane + 32*q;
                uint4 w1u = __ldg(wr + m);           // h-part elems [8m,8m+8)
                uint4 w2u = __ldg(wr + 128 + m);     // x-part
                float c1[8], c2c[8];
                unpk8(w1u, c1); unpk8(w2u, c2c);
                #pragma unroll
                for (int k = 0; k < KB; k++){
                    float4 ha = hs[k*256+2*m], hb = hs[k*256+2*m+1];
                    float4 xa = xs[k*256+2*m], xb = xs[k*256+2*m+1];
                    acc[k] += c1[0]*ha.x + c1[1]*ha.y + c1[2]*ha.z + c1[3]*ha.w
                            + c1[4]*hb.x + c1[5]*hb.y + c1[6]*hb.z + c1[7]*hb.w
                            + c2c[0]*xa.x + c2c[1]*xa.y + c2c[2]*xa.z + c2c[3]*xa.w
                            + c2c[4]*xb.x + c2c[5]*xb.y + c2c[6]*xb.z + c2c[7]*xb.w;
                }
            }
            #pragma unroll
            for (int o = 16; o; o >>= 1)
                #pragma unroll
                for (int k = 0; k < KB; k++)
                    acc[k] += __shfl_xor_sync(0xffffffffu, acc[k], o);
            if (lane == 0){
                float bb = __ldg(&bcat[j]);
                #pragma unroll
                for (int k = 0; k < KB; k++)
                    g_o[k*HD2+j] = tanhf(acc[k] + bb);
            }
        }
        gbar();

        // -------- C: logits from L2-resident bf16 W_out (4 rows/warp) --------
        float4* os = smem4;   // [4][256]
        for (int i = tid; i < KB*HD2; i += NT) ((float*)os)[i] = __ldcg(&g_o[i]);
        __syncthreads();
        {
            float mw[KB] = {-FLT_MAX,-FLT_MAX,-FLT_MAX,-FLT_MAX};
            float sw[KB] = {0.f,0.f,0.f,0.f};
            for (int v0 = gwarp*4; v0 < VV; v0 += NWARP*4){
                float acc[4][KB];
                #pragma unroll
                for (int r = 0; r < 4; r++)
                    #pragma unroll
                    for (int k = 0; k < KB; k++) acc[r][k] = 0.f;
                #pragma unroll
                for (int q = 0; q < 4; q++){
                    int m = lane + 32*q;
                    float4 oa[KB], ob[KB];
                    #pragma unroll
                    for (int k = 0; k < KB; k++){
                        oa[k] = os[k*256 + 2*m];
                        ob[k] = os[k*256 + 2*m + 1];
                    }
                    #pragma unroll
                    for (int r = 0; r < 4; r++){
                        uint4 w = __ldg((const uint4*)g_Wbfu + (size_t)(v0+r)*128 + m);
                        float c[8];
                        unpk8(w, c);
                        #pragma unroll
                        for (int k = 0; k < KB; k++){
                            acc[r][k] += c[0]*oa[k].x + c[1]*oa[k].y + c[2]*oa[k].z + c[3]*oa[k].w
                                       + c[4]*ob[k].x + c[5]*ob[k].y + c[6]*ob[k].z + c[7]*ob[k].w;
                        }
                    }
                }
                #pragma unroll
                for (int o = 16; o; o >>= 1)
                    #pragma unroll
                    for (int r = 0; r < 4; r++)
                        #pragma unroll
                        for (int k = 0; k < KB; k++)
                            acc[r][k] += __shfl_xor_sync(0xffffffffu, acc[r][k], o);
                if (lane == 0){
                    #pragma unroll
                    for (int r = 0; r < 4; r++){
                        float bo = __ldg(&bout[v0+r]);
                        #pragma unroll
                        for (int k = 0; k < KB; k++){
                            float l = acc[r][k] + bo;
                            g_logits[(size_t)k*VV + v0 + r] = l;
                            if (l > mw[k]){ sw[k] = sw[k]*expf(mw[k]-l) + 1.f; mw[k] = l; }
                            else          { sw[k] += expf(l - mw[k]); }
                        }
                    }
                }
            }
            if (lane == 0)
                #pragma unroll
                for (int k = 0; k < KB; k++){ sm_m[wid][k] = mw[k]; sm_s[wid][k] = sw[k]; }
            __syncthreads();
            if (tid < KB){
                const int k = tid;
                float m = -FLT_MAX, s = 0.f;
                #pragma unroll
                for (int w = 0; w < 8; w++){
                    float mwv = sm_m[w][k], swv = sm_s[w][k];
                    if (mwv > m){ s = s*expf(m-mwv) + swv; m = mwv; }
                    else        { s += swv*expf(mwv-m); }
                }
                g_pmax[bid*KB+k] = m;
                g_psum[bid*KB+k] = s;
            }
        }
        gbar();

        // -------- E: global (m,S); sc=ftz chain; per-block top-4 --------
        if (wid < KB){
            const int k = wid;
            float mloc = -FLT_MAX;
            for (int i = lane; i < NB; i += 32)
                mloc = fmaxf(mloc, __ldcg(&g_pmax[i*KB+k]));
            #pragma unroll
            for (int o = 16; o; o >>= 1) mloc = fmaxf(mloc, __shfl_xor_sync(0xffffffffu, mloc, o));
            float sloc = 0.f;
            for (int i = lane; i < NB; i += 32){
                float mb = __ldcg(&g_pmax[i*KB+k]);
                float sb = __ldcg(&g_psum[i*KB+k]);
                sloc += sb*expf(mb - mloc);
            }
            #pragma unroll
            for (int o = 16; o; o >>= 1) sloc += __shfl_xor_sync(0xffffffffu, sloc, o);
            if (lane == 0){ s_gmax[k] = mloc; s_S[k] = sloc; }
        }
        __syncthreads();
        {
            float tv[4] = {-FLT_MAX,-FLT_MAX,-FLT_MAX,-FLT_MAX};
            int   ti[4] = {0x7fffffff,0x7fffffff,0x7fffffff,0x7fffffff};
            for (int v = bid*NT + tid; v < VV; v += NB*NT){
                #pragma unroll
                for (int k = 0; k < KB; k++){
                    float l  = __ldcg(&g_logits[(size_t)k*VV+v]);
                    float e  = ftz(expf(l - s_gmax[k]));
                    float pf = ftz(__fdiv_rn(e, s_S[k]));
                    float sc = ftz(__fmul_rn(s_bp[k], pf));
                    ins4(sc, k*VV+v, tv, ti);
                }
            }
            warp_merge4(tv, ti);
            if (lane == 0)
                #pragma unroll
                for (int j = 0; j < 4; j++){ scv[wid*4+j]=tv[j]; sci[wid*4+j]=ti[j]; }
            __syncthreads();
            if (tid == 0){
                float bv[4] = {-FLT_MAX,-FLT_MAX,-FLT_MAX,-FLT_MAX};
                int   bix[4] = {0x7fffffff,0x7fffffff,0x7fffffff,0x7fffffff};
                for (int i = 0; i < 32; i++) ins4(scv[i], sci[i], bv, bix);
                #pragma unroll
                for (int j = 0; j < 4; j++){ g_candv[bid*4+j]=bv[j]; g_candi[bid*4+j]=bix[j]; }
            }
        }
        gbar();
    }

    // =============== final selection + output ===============
    if (wid == 0){
        float tv[4] = {-FLT_MAX,-FLT_MAX,-FLT_MAX,-FLT_MAX};
        int   ti[4] = {0x7fffffff,0x7fffffff,0x7fffffff,0x7fffffff};
        for (int i = lane; i < NB*KB; i += 32)
            ins4(__ldcg(&g_candv[i]), __ldcg(&g_candi[i]), tv, ti);
        warp_merge4(tv, ti);
        if (lane == 0)
            #pragma unroll
            for (int j = 0; j < 4; j++){
                int idx = ti[j];
                s_bi2[j] = idx / VV;
                s_tok[j] = idx - (idx/VV)*VV;
                s_bp[j]  = tv[j];
            }
    }
    __syncthreads();
    if (bid == 0){
        if (tid < KB*(ML+1)){
            int kk = tid/(ML+1), col = tid%(ML+1);
            int val = (col == ML) ? s_tok[kk]
                                  : g_tok[(ML-1)&1][s_bi2[kk]*(ML+1)+col];
            out[tid] = (float)val;
        }
        if (out_size >= KB*(ML+1)+KB && tid < KB)
            out[KB*(ML+1)+tid] = s_bp[tid];
    }
}

// ---------------- host ----------------
static int pick_idx(const int* sz, int n, int want, int occ){
    int c = 0;
    for (int i = 0; i < n; i++)
        if (sz[i] == want){ if (c == occ) return i; c++; }
    return -1;
}

extern "C" void kernel_launch(void* const* d_in, const int* in_sizes, int n_in,
                              void* d_out, int out_size)
{
    int iv   = pick_idx(in_sizes, n_in, TT*DIN, 0);
    int ie   = pick_idx(in_sizes, n_in, VV*HD2, 0);
    int iWf  = pick_idx(in_sizes, n_in, GE*DIN, 0);
    int iHf  = pick_idx(in_sizes, n_in, GE*HH, 0);
    int ibf  = pick_idx(in_sizes, n_in, GE, 0);
    int iWb  = pick_idx(in_sizes, n_in, GE*DIN, 1);
    int ibb  = pick_idx(in_sizes, n_in, GE, 1);
    int idW  = pick_idx(in_sizes, n_in, 4*HD2*HD2, 0);
    int idH  = pick_idx(in_sizes, n_in, 4*HD2*HD2, 1);
    int idb  = pick_idx(in_sizes, n_in, 4*HD2, 0);
    int iWc  = pick_idx(in_sizes, n_in, HD2*2*HD2, 0);
    int ibc  = pick_idx(in_sizes, n_in, HD2, 0);
    int iWo  = pick_idx(in_sizes, n_in, VV*HD2, 1);
    int ibo  = pick_idx(in_sizes, n_in, VV, 0);
    if (iv<0||ie<0||iWf<0||iHf<0||ibf<0||iWb<0||ibb<0||idW<0||idH<0||idb<0||iWc<0||ibc<0||iWo<0||ibo<0){
        iv=0; ie=1; iWf=2; iHf=3; ibf=4; iWb=5; ibb=7; idW=8; idH=9; idb=10; iWc=11; ibc=12; iWo=13; ibo=14;
    }
    beam_kernel<<<NB, NT>>>(
        (const float*)d_in[iv],  (const float*)d_in[ie],
        (const float*)d_in[iWf], (const float*)d_in[iHf], (const float*)d_in[ibf],
        (const float*)d_in[iWb], (const float*)d_in[ibb],
        (const float*)d_in[idW], (const float*)d_in[idH], (const float*)d_in[idb],
        (const float*)d_in[iWc], (const float*)d_in[ibc],
        (const float*)d_in[iWo], (const float*)d_in[ibo],
        (float*)d_out, out_size);
}